// round 15
// baseline (speedup 1.0000x reference)
#include <cuda_runtime.h>
#include <cuda_bf16.h>
#include <math.h>
#include <stdint.h>

#define N_NODES 10000
#define N_EDGES 320000
#define MUL 32

__device__ __align__(16) float g_wkv [N_EDGES * 256];   // per-edge MLP outputs [wk(128)|wv(128)]
__device__ __align__(16) float g_qpre[N_NODES * 1024];  // per-node precomputed query side
__device__ __align__(16) float g_z   [N_NODES * 4];     // attention normalizer per head
__device__ __align__(16) float g_agg [N_NODES * 256];   // unnormalized aggregation

#define INV3F 0.57735026918962576f
#define INVFAN 0.015625f

// ---------------------------------------------------------------- f32x2 helpers
__device__ __forceinline__ uint64_t pack2(float lo, float hi) {
    uint64_t r; asm("mov.b64 %0, {%1, %2};" : "=l"(r) : "f"(lo), "f"(hi)); return r;
}
__device__ __forceinline__ void unpack2(uint64_t v, float& lo, float& hi) {
    asm("mov.b64 {%0, %1}, %2;" : "=f"(lo), "=f"(hi) : "l"(v));
}
__device__ __forceinline__ void fmaX2(uint64_t& c, uint64_t a, uint64_t b) {
    asm("fma.rn.f32x2 %0, %1, %2, %0;" : "+l"(c) : "l"(a), "l"(b));
}

// ---------------------------------------------------------------- zero scratch
__global__ void ek_zero_kernel() {
    int i = blockIdx.x * blockDim.x + threadIdx.x;
    int stride = gridDim.x * blockDim.x;
    float4 z4 = make_float4(0.f, 0.f, 0.f, 0.f);
    for (int j = i; j < N_NODES * 64; j += stride) ((float4*)g_agg)[j] = z4;
    for (int j = i; j < N_NODES;      j += stride) ((float4*)g_z)[j]   = z4;
}

// ---------------------------------------------------------------- Qpre precompute
__global__ void __launch_bounds__(256) ek_qpre_kernel(const float* __restrict__ nodef,
                                                      const float* __restrict__ wdot,
                                                      int nbase) {
    extern __shared__ float qsm[];
    float* s_w = qsm;            // 16384 floats
    float* s_x = qsm + 16384;    // 128 floats
    int t = threadIdx.x;
    for (int i = t; i < 16384; i += 256) s_w[i] = wdot[i];
    for (int nn = 0; nn < 10; nn++) {
        int n = nbase + blockIdx.x * 10 + nn;
        __syncthreads();
        if (t < 32) *(float4*)&s_x[t * 4] = *(const float4*)(nodef + (size_t)n * 128 + t * 4);
        __syncthreads();
#pragma unroll
        for (int rep = 0; rep < 4; rep++) {
            int o = t + rep * 256;
            int h = o >> 8, i = o & 255;
            float acc = 0.f;
            if (i < 64) {
                int p = (i < 32) ? 0 : 1;
                int v = i & 31;
                const float* W = s_w + (p * 4 + h) * 1024 + v;
#pragma unroll
                for (int u = 0; u < 32; u++) acc += s_x[u] * W[u * 32];
                acc *= INVFAN;
            } else {
                int p  = (i < 160) ? 2 : 3;
                int tt = (i < 160) ? (i - 64) : (i - 160);
                int d = tt >> 5, v = tt & 31;
                const float* W = s_w + (p * 4 + h) * 1024 + v;
#pragma unroll
                for (int u = 0; u < 32; u++) acc += s_x[32 + 3 * u + d] * W[u * 32];
                acc *= INVFAN * INV3F;
            }
            g_qpre[(size_t)n * 1024 + o] = acc;
        }
    }
}

// ---------------------------------------------------------------- f32x2 dual MLP v6
// grid (2500, 2): 128 edges x one part. 256 threads, 2 CTAs/SM (100.6KB smem).
// Layer1 scalar 8->64 + gelu into s_h[k][e] f32 (edge-pairs u64-reinterpretable).
// Layer2: tile 4 edge-pairs x 8 outputs. Per k: 2 LDS.128 h (direct u64, no
// movs) + 4 LDS.128 w (PRE-DUPLICATED (w,w) u64 in smem, no movs) + 32 FFMA2
// -> 84% FMA issue mix (R8 was 67% with 12 movs/k).
// smem: s_h 32768 | s_w2d 65536 | s_w1 2048 | s_b1 256 = 100,608 B
#define MLP_SMEM 100608
__global__ void __launch_bounds__(256, 2) ek_mlp_kernel(const float* __restrict__ xattr,
    const float* __restrict__ wk1, const float* __restrict__ bk1, const float* __restrict__ wk2,
    const float* __restrict__ wv1, const float* __restrict__ bv1, const float* __restrict__ wv2) {
    extern __shared__ float sm[];
    float*    s_h   = sm;                         // [64 k][128 e] f32
    uint64_t* s_w2d = (uint64_t*)(sm + 8192);     // [64 k][128 n] (w,w) u64
    float*    s_w1  = sm + 24576;                 // [8][64]
    float*    s_b1  = sm + 25088;                 // [64]
    int t = threadIdx.x;
    int part = blockIdx.y;
    int e0 = blockIdx.x * 128;
    const float* w2g = part ? wv2 : wk2;
    const float* w1g = part ? wv1 : wk1;
    const float* b1g = part ? bv1 : bk1;

    for (int i = t; i < 8192; i += 256) { float w = w2g[i]; s_w2d[i] = pack2(w, w); }
    for (int i = t; i < 512; i += 256) s_w1[i] = w1g[i];
    if (t < 64) s_b1[t] = b1g[t];
    __syncthreads();

    // layer1: e = t&127, half = t>>7 handles 32 channels
    {
        int e = t & 127, half = t >> 7;
        const float4* xp = (const float4*)(xattr + (size_t)(e0 + e) * 8);
        float4 xa = xp[0], xb = xp[1];
#pragma unroll 8
        for (int cc = 0; cc < 32; cc++) {
            int c = half * 32 + cc;
            float acc = xa.x * s_w1[c]       + xa.y * s_w1[64 + c]  + xa.z * s_w1[128 + c] + xa.w * s_w1[192 + c]
                      + xb.x * s_w1[256 + c] + xb.y * s_w1[320 + c] + xb.z * s_w1[384 + c] + xb.w * s_w1[448 + c];
            acc = acc * 0.35355339059327373f + s_b1[c];
            float u2 = 0.7978845608028654f * (acc + 0.044715f * acc * acc * acc);
            float th;
            asm("tanh.approx.f32 %0, %1;" : "=f"(th) : "f"(u2));
            s_h[c * 128 + e] = 0.5f * acc * (1.f + th);
        }
    }
    __syncthreads();

    // layer2: pt = t&15 -> 4 edge-pairs (8 edges), ot = t>>4 -> 8 outputs
    int pt = t & 15, ot = t >> 4;
    const float*    hp = s_h + pt * 8;          // + k*128 (cast to u64 pairs)
    const uint64_t* wp = s_w2d + ot * 8;        // + k*128

    uint64_t acc[4][8];
#pragma unroll
    for (int p = 0; p < 4; p++)
#pragma unroll
        for (int o = 0; o < 8; o++) acc[p][o] = 0ull;

#pragma unroll 4
    for (int k = 0; k < 64; k++) {
        const uint64_t* hu = (const uint64_t*)(hp + (size_t)k * 128);
        ulonglong2 h01 = *(const ulonglong2*)(hu);
        ulonglong2 h23 = *(const ulonglong2*)(hu + 2);
        const uint64_t* wu = wp + (size_t)k * 128;
        ulonglong2 w01 = *(const ulonglong2*)(wu);
        ulonglong2 w23 = *(const ulonglong2*)(wu + 2);
        ulonglong2 w45 = *(const ulonglong2*)(wu + 4);
        ulonglong2 w67 = *(const ulonglong2*)(wu + 6);
        uint64_t hx[4] = { h01.x, h01.y, h23.x, h23.y };
        uint64_t wd[8] = { w01.x, w01.y, w23.x, w23.y, w45.x, w45.y, w67.x, w67.y };
#pragma unroll
        for (int p = 0; p < 4; p++)
#pragma unroll
            for (int o = 0; o < 8; o++) fmaX2(acc[p][o], hx[p], wd[o]);
    }

    const float inv64 = 0.125f;
    int col = part * 128 + ot * 8;
#pragma unroll
    for (int p = 0; p < 4; p++) {
        int elo = e0 + pt * 8 + p * 2;
        float lo[8], hi[8];
#pragma unroll
        for (int o = 0; o < 8; o++) { unpack2(acc[p][o], lo[o], hi[o]); lo[o] *= inv64; hi[o] *= inv64; }
        float* d0 = g_wkv + (size_t)elo * 256 + col;
        float* d1 = d0 + 256;
        __stcs((float4*)d0,       make_float4(lo[0], lo[1], lo[2], lo[3]));
        __stcs((float4*)(d0 + 4), make_float4(lo[4], lo[5], lo[6], lo[7]));
        __stcs((float4*)d1,       make_float4(hi[0], hi[1], hi[2], hi[3]));
        __stcs((float4*)(d1 + 4), make_float4(hi[4], hi[5], hi[6], hi[7]));
    }
}

// ---------------------------------------------------------------- edge megakernel (atomic, measured 213us)
__device__ __forceinline__ float feat_base(int i, const float* row,
                                           float ys, float yv0, float yv1, float yv2,
                                           int& widx) {
    if (i < 32) { widx = i; return row[i] * ys; }
    if (i < 64) {
        int u = i - 32; widx = i;
        return (row[32 + 3 * u] * yv0 + row[33 + 3 * u] * yv1 + row[34 + 3 * u] * yv2) * INV3F;
    }
    if (i < 160) {
        int tt = i - 64; int d = tt >> 5, u = tt & 31; widx = 64 + u;
        float yd = (d == 0) ? yv0 : ((d == 1) ? yv1 : yv2);
        return row[u] * yd;
    }
    {
        int tt = i - 160; int d = tt >> 5, u = tt & 31; widx = 96 + u;
        return row[32 + 3 * u + d] * ys;
    }
}
__device__ __forceinline__ int feat_head(int i) {
    if (i < 64) return (i & 31) >> 3;
    int tt = (i < 160) ? (i - 64) : (i - 160);
    return (tt & 31) >> 3;
}
__device__ __forceinline__ void red_v4(float* p, float a, float b, float c, float d) {
    asm volatile("red.global.add.v4.f32 [%0], {%1, %2, %3, %4};"
                 :: "l"(p), "f"(a), "f"(b), "f"(c), "f"(d) : "memory");
}

__global__ void __launch_bounds__(256) ek_edge_kernel(
    const int* __restrict__ esrc, const int* __restrict__ edst,
    const float* __restrict__ eattr, const float* __restrict__ ecut,
    const float* __restrict__ nodef) {
    __shared__ float s_row[8][136];
    __shared__ float s_w[8][256];
    int warp = threadIdx.x >> 5, lane = threadIdx.x & 31;
    int e = blockIdx.x * 8 + warp;
    if (e >= N_EDGES) return;

    int s = esrc[e], dd = edst[e];
    float4 ea = *(const float4*)(eattr + (size_t)e * 4);
    float ys = ea.x, yv0 = ea.y, yv1 = ea.z, yv2 = ea.w;
    float cw = ecut[e];

    *(float4*)&s_row[warp][lane * 4] = *(const float4*)(nodef + (size_t)s * 128 + lane * 4);
    const float4* wv4 = (const float4*)(g_wkv + (size_t)e * 256);
    *(float4*)&s_w[warp][lane * 4]       = __ldcs(wv4 + lane);
    *(float4*)&s_w[warp][128 + lane * 4] = __ldcs(wv4 + 32 + lane);
    __syncwarp();

    const float* row = s_row[warp];
    const float* wk  = s_w[warp];
    int iA = 4 * lane, iB = 128 + 4 * lane;

    float bA[4], bB[4];
    int   xA[4], xB[4];
#pragma unroll
    for (int j = 0; j < 4; j++) {
        bA[j] = feat_base(iA + j, row, ys, yv0, yv1, yv2, xA[j]);
        bB[j] = feat_base(iB + j, row, ys, yv0, yv1, yv2, xB[j]);
    }

    float kA[4], kB[4];
#pragma unroll
    for (int j = 0; j < 4; j++) { kA[j] = wk[xA[j]] * bA[j]; kB[j] = wk[xB[j]] * bB[j]; }

    const float4* q = (const float4*)(g_qpre + (size_t)dd * 1024);
    float dh[4];
#pragma unroll
    for (int h = 0; h < 4; h++) {
        float4 qa = q[h * 64 + lane];
        float4 qb = q[h * 64 + 32 + lane];
        dh[h] = qa.x * kA[0] + qa.y * kA[1] + qa.z * kA[2] + qa.w * kA[3]
              + qb.x * kB[0] + qb.y * kB[1] + qb.z * kB[2] + qb.w * kB[3];
    }
#pragma unroll
    for (int off = 16; off; off >>= 1) {
#pragma unroll
        for (int h = 0; h < 4; h++) dh[h] += __shfl_xor_sync(0xffffffffu, dh[h], off);
    }

    float ew[4], sa[4];
#pragma unroll
    for (int h = 0; h < 4; h++) {
        ew[h] = cw * expf(dh[h]);
        sa[h] = sqrtf(ew[h]);     // sqrt(expw); /sqrt(z) deferred to epilogue
    }
    if (lane == 0) red_v4(g_z + (size_t)dd * 4, ew[0], ew[1], ew[2], ew[3]);

    const float* wv = wk + 128;
    float vA[4], vB[4];
#pragma unroll
    for (int j = 0; j < 4; j++) {
        vA[j] = wv[xA[j]] * bA[j] * sa[feat_head(iA + j)];
        vB[j] = wv[xB[j]] * bB[j] * sa[feat_head(iB + j)];
    }
    red_v4(g_agg + (size_t)dd * 256 + iA, vA[0], vA[1], vA[2], vA[3]);
    red_v4(g_agg + (size_t)dd * 256 + iB, vB[0], vB[1], vB[2], vB[3]);
}

// ---------------------------------------------------------------- node epilogue
__global__ void __launch_bounds__(128) ek_out_kernel(const float* __restrict__ wls,
                                                     const float* __restrict__ wlv,
                                                     float* __restrict__ out) {
    __shared__ float s_ws[2048];
    __shared__ float s_wv[2048];
    __shared__ float s_s[64];
    __shared__ float s_v[192];
    __shared__ float s_sc[4];
    int t = threadIdx.x;
    for (int i = t; i < 2048; i += 128) { s_ws[i] = wls[i]; s_wv[i] = wlv[i]; }
    const float inv_l = 0.125f;

    for (int nn = 0; nn < 10; nn++) {
        int n = blockIdx.x * 10 + nn;
        __syncthreads();
        if (t < 4) {
            float zz = g_z[(size_t)n * 4 + t];
            s_sc[t] = (zz == 0.f) ? 1.f : (1.0f / sqrtf(zz));
        }
        __syncthreads();
        for (int i = t; i < 256; i += 128) {
            float val = g_agg[(size_t)n * 256 + i];
            if (i < 64) {
                s_s[i] = val * s_sc[(i & 31) >> 3];
            } else {
                int f = i - 64;
                int blk = (f < 96) ? 0 : 1;
                int r = f - blk * 96;
                int d = r >> 5, uu = r & 31;
                s_v[d * 64 + blk * 32 + uu] = val * s_sc[uu >> 3];
            }
        }
        __syncthreads();
        if (t < 32) {
            int w = t;
            float acc = 0.f;
#pragma unroll
            for (int u = 0; u < 64; u++) acc += s_s[u] * s_ws[u * 32 + w];
            out[(size_t)n * 128 + w] = acc * inv_l;
        } else {
            int o = t - 32;
            int d = o >> 5, w = o & 31;
            float acc = 0.f;
#pragma unroll
            for (int u = 0; u < 64; u++) acc += s_v[d * 64 + u] * s_wv[u * 32 + w];
            out[(size_t)n * 128 + 32 + w * 3 + d] = acc * inv_l;
        }
    }
}

// ---------------------------------------------------------------- launch
extern "C" void kernel_launch(void* const* d_in, const int* in_sizes, int n_in,
                              void* d_out, int out_size) {
    const int*   esrc  = (const int*)d_in[0];
    const int*   edst  = (const int*)d_in[1];
    const float* xattr = (const float*)d_in[2];
    const float* eattr = (const float*)d_in[3];
    const float* ecut  = (const float*)d_in[4];
    const float* nodef = (const float*)d_in[5];
    const float* wk1   = (const float*)d_in[6];
    const float* bk1   = (const float*)d_in[7];
    const float* wk2   = (const float*)d_in[8];
    const float* wv1   = (const float*)d_in[9];
    const float* bv1   = (const float*)d_in[10];
    const float* wv2   = (const float*)d_in[11];
    const float* wdot  = (const float*)d_in[12];
    const float* wls   = (const float*)d_in[13];
    const float* wlv   = (const float*)d_in[14];
    float* out = (float*)d_out;

    const int qpre_smem = 16512 * 4;   // 66,048 B
    cudaFuncSetAttribute(ek_qpre_kernel, cudaFuncAttributeMaxDynamicSharedMemorySize, qpre_smem);
    cudaFuncSetAttribute(ek_mlp_kernel,  cudaFuncAttributeMaxDynamicSharedMemorySize, MLP_SMEM);

    // launch index 3 (ncu capture slot) = ek_mlp_kernel
    ek_zero_kernel<<<1024, 256>>>();
    ek_qpre_kernel<<<500, 256, qpre_smem>>>(nodef, wdot, 0);
    ek_qpre_kernel<<<500, 256, qpre_smem>>>(nodef, wdot, 5000);
    dim3 mgrid(2500, 2);
    ek_mlp_kernel<<<mgrid, 256, MLP_SMEM>>>(xattr, wk1, bk1, wk2, wv1, bv1, wv2);
    ek_edge_kernel<<<N_EDGES / 8, 256>>>(esrc, edst, eattr, ecut, nodef);
    ek_out_kernel<<<N_NODES / 10, 128>>>(wls, wlv, out);
}

// round 16
// speedup vs baseline: 1.0612x; 1.0612x over previous
#include <cuda_runtime.h>
#include <cuda_bf16.h>
#include <math.h>
#include <stdint.h>

#define N_NODES 10000
#define N_EDGES 320000
#define MUL 32

__device__ __align__(16) float g_wkv [N_EDGES * 256];   // per-edge MLP outputs [wk(128)|wv(128)]
__device__ __align__(16) float g_qpre[N_NODES * 1024];  // per-node precomputed query side
__device__ __align__(16) float g_z   [N_NODES * 4];     // attention normalizer per head
__device__ __align__(16) float g_agg [N_NODES * 256];   // unnormalized aggregation

#define INV3F 0.57735026918962576f
#define INVFAN 0.015625f

// ---------------------------------------------------------------- f32x2 helpers
__device__ __forceinline__ uint64_t pack2(float lo, float hi) {
    uint64_t r; asm("mov.b64 %0, {%1, %2};" : "=l"(r) : "f"(lo), "f"(hi)); return r;
}
__device__ __forceinline__ void unpack2(uint64_t v, float& lo, float& hi) {
    asm("mov.b64 {%0, %1}, %2;" : "=f"(lo), "=f"(hi) : "l"(v));
}
__device__ __forceinline__ void fmaX2(uint64_t& c, uint64_t a, uint64_t b) {
    asm("fma.rn.f32x2 %0, %1, %2, %0;" : "+l"(c) : "l"(a), "l"(b));
}

// ---------------------------------------------------------------- zero scratch
__global__ void ek_zero_kernel() {
    int i = blockIdx.x * blockDim.x + threadIdx.x;
    int stride = gridDim.x * blockDim.x;
    float4 z4 = make_float4(0.f, 0.f, 0.f, 0.f);
    for (int j = i; j < N_NODES * 64; j += stride) ((float4*)g_agg)[j] = z4;
    for (int j = i; j < N_NODES;      j += stride) ((float4*)g_z)[j]   = z4;
}

// ---------------------------------------------------------------- Qpre precompute
__global__ void __launch_bounds__(256) ek_qpre_kernel(const float* __restrict__ nodef,
                                                      const float* __restrict__ wdot,
                                                      int nbase) {
    extern __shared__ float qsm[];
    float* s_w = qsm;            // 16384 floats
    float* s_x = qsm + 16384;    // 128 floats
    int t = threadIdx.x;
    for (int i = t; i < 16384; i += 256) s_w[i] = wdot[i];
    for (int nn = 0; nn < 10; nn++) {
        int n = nbase + blockIdx.x * 10 + nn;
        __syncthreads();
        if (t < 32) *(float4*)&s_x[t * 4] = *(const float4*)(nodef + (size_t)n * 128 + t * 4);
        __syncthreads();
#pragma unroll
        for (int rep = 0; rep < 4; rep++) {
            int o = t + rep * 256;
            int h = o >> 8, i = o & 255;
            float acc = 0.f;
            if (i < 64) {
                int p = (i < 32) ? 0 : 1;
                int v = i & 31;
                const float* W = s_w + (p * 4 + h) * 1024 + v;
#pragma unroll
                for (int u = 0; u < 32; u++) acc += s_x[u] * W[u * 32];
                acc *= INVFAN;
            } else {
                int p  = (i < 160) ? 2 : 3;
                int tt = (i < 160) ? (i - 64) : (i - 160);
                int d = tt >> 5, v = tt & 31;
                const float* W = s_w + (p * 4 + h) * 1024 + v;
#pragma unroll
                for (int u = 0; u < 32; u++) acc += s_x[32 + 3 * u + d] * W[u * 32];
                acc *= INVFAN * INV3F;
            }
            g_qpre[(size_t)n * 1024 + o] = acc;
        }
    }
}

// ---------------------------------------------------------------- f32x2 dual MLP (R8 + h-swizzle)
// 64 edges/block, 256 threads, 2 CTAs/SM. Identical to the measured-326us R8
// kernel EXCEPT s_h rows are 68 floats with the second 32-edge half offset by
// +4 floats: load addresses across pt hit all 8 bank groups (0,32,64,96 ->
// groups 0/2/4/6; 144,176,208,240 -> groups 1/3/5/7) -> h LDS conflict-free
// (was 2-way). W path unchanged (f32 + register dup — crossbar-cheap).
// smem floats: s_h[128][68] @0 (34816B) | s_w2[64][256] @8704 (64KB)
//              | s_w1 @25088 | s_b1 @26112  => 104,960 B
#define HS 68
#define MLP_SMEM 104960
__global__ void __launch_bounds__(256, 2) ek_mlp_kernel(const float* __restrict__ xattr,
    const float* __restrict__ wk1, const float* __restrict__ bk1, const float* __restrict__ wk2,
    const float* __restrict__ wv1, const float* __restrict__ bv1, const float* __restrict__ wv2) {
    extern __shared__ float sm[];
    float* s_h  = sm;                 // [128 c][68] swizzled
    float* s_w2 = sm + 8704;          // [64 k][256 n]
    float* s_w1 = sm + 25088;
    float* s_b1 = sm + 26112;
    int t = threadIdx.x;
    int e0 = blockIdx.x * 64;

    for (int i = t; i < 8192; i += 256) {
        int k = i >> 7, n = i & 127;
        s_w2[k * 256 + n]       = wk2[i];
        s_w2[k * 256 + 128 + n] = wv2[i];
    }
    for (int i = t; i < 1024; i += 256) s_w1[i] = (i < 512) ? wk1[i] : wv1[i - 512];
    if (t < 128) s_b1[t] = (t < 64) ? bk1[t] : bv1[t - 64];
    __syncthreads();

    // layer1: thread -> (edge e, group grp); grp: part=grp>>1, cbase=(grp&1)*32
    {
        int e = t & 63, grp = t >> 6;
        int part = grp >> 1, cb = (grp & 1) * 32;
        const float4* xp = (const float4*)(xattr + (size_t)(e0 + e) * 8);
        float4 xa = xp[0], xb = xp[1];
        const float* w1 = s_w1 + part * 512;
        const float* bb = s_b1 + part * 64;
        int esw = e + ((e >> 5) << 2);           // +4 for e>=32
        float* hout = s_h + (part * 64 + cb) * HS + esw;
#pragma unroll 8
        for (int cc = 0; cc < 32; cc++) {
            int c = cb + cc;
            float acc = xa.x * w1[c]       + xa.y * w1[64 + c]  + xa.z * w1[128 + c] + xa.w * w1[192 + c]
                      + xb.x * w1[256 + c] + xb.y * w1[320 + c] + xb.z * w1[384 + c] + xb.w * w1[448 + c];
            acc = acc * 0.35355339059327373f + bb[c];
            float u2 = 0.7978845608028654f * (acc + 0.044715f * acc * acc * acc);
            float th;
            asm("tanh.approx.f32 %0, %1;" : "=f"(th) : "f"(u2));
            hout[cc * HS] = 0.5f * acc * (1.f + th);
        }
    }
    __syncthreads();

    // layer2: pairtile pt = t&7 (8 edges), outtile ot = t>>3 (8 outs)
    int pt = t & 7, ot = t >> 3;
    int eoff = pt * 8 + ((pt >= 4) ? 4 : 0);     // swizzled edge base
    const float* hp = s_h + ((ot >= 16) ? 64 * HS : 0) + eoff;
    const float* wp = s_w2 + ot * 8;
    uint64_t acc[4][8];
#pragma unroll
    for (int p = 0; p < 4; p++)
#pragma unroll
        for (int o = 0; o < 8; o++) acc[p][o] = 0ull;

#pragma unroll 8
    for (int k = 0; k < 64; k++) {
        float4 h0 = *(const float4*)(hp + k * HS);
        float4 h1 = *(const float4*)(hp + k * HS + 4);
        float4 w0 = *(const float4*)(wp + k * 256);
        float4 w1v = *(const float4*)(wp + k * 256 + 4);
        uint64_t hx[4] = { pack2(h0.x, h0.y), pack2(h0.z, h0.w),
                           pack2(h1.x, h1.y), pack2(h1.z, h1.w) };
        uint64_t wd[8] = { pack2(w0.x, w0.x), pack2(w0.y, w0.y), pack2(w0.z, w0.z), pack2(w0.w, w0.w),
                           pack2(w1v.x, w1v.x), pack2(w1v.y, w1v.y), pack2(w1v.z, w1v.z), pack2(w1v.w, w1v.w) };
#pragma unroll
        for (int p = 0; p < 4; p++)
#pragma unroll
            for (int o = 0; o < 8; o++) fmaX2(acc[p][o], hx[p], wd[o]);
    }

    const float inv64 = 0.125f;
    int n0 = ot * 8;
#pragma unroll
    for (int p = 0; p < 4; p++) {
        int elo = e0 + pt * 8 + p * 2;
        float lo[8], hi[8];
#pragma unroll
        for (int o = 0; o < 8; o++) { unpack2(acc[p][o], lo[o], hi[o]); lo[o] *= inv64; hi[o] *= inv64; }
        float* d0 = g_wkv + (size_t)elo * 256 + n0;
        float* d1 = d0 + 256;
        __stcs((float4*)d0,       make_float4(lo[0], lo[1], lo[2], lo[3]));
        __stcs((float4*)(d0 + 4), make_float4(lo[4], lo[5], lo[6], lo[7]));
        __stcs((float4*)d1,       make_float4(hi[0], hi[1], hi[2], hi[3]));
        __stcs((float4*)(d1 + 4), make_float4(hi[4], hi[5], hi[6], hi[7]));
    }
}

// ---------------------------------------------------------------- edge megakernel (atomic, measured 213us)
__device__ __forceinline__ float feat_base(int i, const float* row,
                                           float ys, float yv0, float yv1, float yv2,
                                           int& widx) {
    if (i < 32) { widx = i; return row[i] * ys; }
    if (i < 64) {
        int u = i - 32; widx = i;
        return (row[32 + 3 * u] * yv0 + row[33 + 3 * u] * yv1 + row[34 + 3 * u] * yv2) * INV3F;
    }
    if (i < 160) {
        int tt = i - 64; int d = tt >> 5, u = tt & 31; widx = 64 + u;
        float yd = (d == 0) ? yv0 : ((d == 1) ? yv1 : yv2);
        return row[u] * yd;
    }
    {
        int tt = i - 160; int d = tt >> 5, u = tt & 31; widx = 96 + u;
        return row[32 + 3 * u + d] * ys;
    }
}
__device__ __forceinline__ int feat_head(int i) {
    if (i < 64) return (i & 31) >> 3;
    int tt = (i < 160) ? (i - 64) : (i - 160);
    return (tt & 31) >> 3;
}
__device__ __forceinline__ void red_v4(float* p, float a, float b, float c, float d) {
    asm volatile("red.global.add.v4.f32 [%0], {%1, %2, %3, %4};"
                 :: "l"(p), "f"(a), "f"(b), "f"(c), "f"(d) : "memory");
}

__global__ void __launch_bounds__(256) ek_edge_kernel(
    const int* __restrict__ esrc, const int* __restrict__ edst,
    const float* __restrict__ eattr, const float* __restrict__ ecut,
    const float* __restrict__ nodef) {
    __shared__ float s_row[8][136];
    __shared__ float s_w[8][256];
    int warp = threadIdx.x >> 5, lane = threadIdx.x & 31;
    int e = blockIdx.x * 8 + warp;
    if (e >= N_EDGES) return;

    int s = esrc[e], dd = edst[e];
    float4 ea = *(const float4*)(eattr + (size_t)e * 4);
    float ys = ea.x, yv0 = ea.y, yv1 = ea.z, yv2 = ea.w;
    float cw = ecut[e];

    *(float4*)&s_row[warp][lane * 4] = *(const float4*)(nodef + (size_t)s * 128 + lane * 4);
    const float4* wv4 = (const float4*)(g_wkv + (size_t)e * 256);
    *(float4*)&s_w[warp][lane * 4]       = __ldcs(wv4 + lane);
    *(float4*)&s_w[warp][128 + lane * 4] = __ldcs(wv4 + 32 + lane);
    __syncwarp();

    const float* row = s_row[warp];
    const float* wk  = s_w[warp];
    int iA = 4 * lane, iB = 128 + 4 * lane;

    float bA[4], bB[4];
    int   xA[4], xB[4];
#pragma unroll
    for (int j = 0; j < 4; j++) {
        bA[j] = feat_base(iA + j, row, ys, yv0, yv1, yv2, xA[j]);
        bB[j] = feat_base(iB + j, row, ys, yv0, yv1, yv2, xB[j]);
    }

    float kA[4], kB[4];
#pragma unroll
    for (int j = 0; j < 4; j++) { kA[j] = wk[xA[j]] * bA[j]; kB[j] = wk[xB[j]] * bB[j]; }

    const float4* q = (const float4*)(g_qpre + (size_t)dd * 1024);
    float dh[4];
#pragma unroll
    for (int h = 0; h < 4; h++) {
        float4 qa = q[h * 64 + lane];
        float4 qb = q[h * 64 + 32 + lane];
        dh[h] = qa.x * kA[0] + qa.y * kA[1] + qa.z * kA[2] + qa.w * kA[3]
              + qb.x * kB[0] + qb.y * kB[1] + qb.z * kB[2] + qb.w * kB[3];
    }
#pragma unroll
    for (int off = 16; off; off >>= 1) {
#pragma unroll
        for (int h = 0; h < 4; h++) dh[h] += __shfl_xor_sync(0xffffffffu, dh[h], off);
    }

    float ew[4], sa[4];
#pragma unroll
    for (int h = 0; h < 4; h++) {
        ew[h] = cw * expf(dh[h]);
        sa[h] = sqrtf(ew[h]);     // sqrt(expw); /sqrt(z) deferred to epilogue
    }
    if (lane == 0) red_v4(g_z + (size_t)dd * 4, ew[0], ew[1], ew[2], ew[3]);

    const float* wv = wk + 128;
    float vA[4], vB[4];
#pragma unroll
    for (int j = 0; j < 4; j++) {
        vA[j] = wv[xA[j]] * bA[j] * sa[feat_head(iA + j)];
        vB[j] = wv[xB[j]] * bB[j] * sa[feat_head(iB + j)];
    }
    red_v4(g_agg + (size_t)dd * 256 + iA, vA[0], vA[1], vA[2], vA[3]);
    red_v4(g_agg + (size_t)dd * 256 + iB, vB[0], vB[1], vB[2], vB[3]);
}

// ---------------------------------------------------------------- node epilogue
__global__ void __launch_bounds__(128) ek_out_kernel(const float* __restrict__ wls,
                                                     const float* __restrict__ wlv,
                                                     float* __restrict__ out) {
    __shared__ float s_ws[2048];
    __shared__ float s_wv[2048];
    __shared__ float s_s[64];
    __shared__ float s_v[192];
    __shared__ float s_sc[4];
    int t = threadIdx.x;
    for (int i = t; i < 2048; i += 128) { s_ws[i] = wls[i]; s_wv[i] = wlv[i]; }
    const float inv_l = 0.125f;

    for (int nn = 0; nn < 10; nn++) {
        int n = blockIdx.x * 10 + nn;
        __syncthreads();
        if (t < 4) {
            float zz = g_z[(size_t)n * 4 + t];
            s_sc[t] = (zz == 0.f) ? 1.f : (1.0f / sqrtf(zz));
        }
        __syncthreads();
        for (int i = t; i < 256; i += 128) {
            float val = g_agg[(size_t)n * 256 + i];
            if (i < 64) {
                s_s[i] = val * s_sc[(i & 31) >> 3];
            } else {
                int f = i - 64;
                int blk = (f < 96) ? 0 : 1;
                int r = f - blk * 96;
                int d = r >> 5, uu = r & 31;
                s_v[d * 64 + blk * 32 + uu] = val * s_sc[uu >> 3];
            }
        }
        __syncthreads();
        if (t < 32) {
            int w = t;
            float acc = 0.f;
#pragma unroll
            for (int u = 0; u < 64; u++) acc += s_s[u] * s_ws[u * 32 + w];
            out[(size_t)n * 128 + w] = acc * inv_l;
        } else {
            int o = t - 32;
            int d = o >> 5, w = o & 31;
            float acc = 0.f;
#pragma unroll
            for (int u = 0; u < 64; u++) acc += s_v[d * 64 + u] * s_wv[u * 32 + w];
            out[(size_t)n * 128 + 32 + w * 3 + d] = acc * inv_l;
        }
    }
}

// ---------------------------------------------------------------- launch
extern "C" void kernel_launch(void* const* d_in, const int* in_sizes, int n_in,
                              void* d_out, int out_size) {
    const int*   esrc  = (const int*)d_in[0];
    const int*   edst  = (const int*)d_in[1];
    const float* xattr = (const float*)d_in[2];
    const float* eattr = (const float*)d_in[3];
    const float* ecut  = (const float*)d_in[4];
    const float* nodef = (const float*)d_in[5];
    const float* wk1   = (const float*)d_in[6];
    const float* bk1   = (const float*)d_in[7];
    const float* wk2   = (const float*)d_in[8];
    const float* wv1   = (const float*)d_in[9];
    const float* bv1   = (const float*)d_in[10];
    const float* wv2   = (const float*)d_in[11];
    const float* wdot  = (const float*)d_in[12];
    const float* wls   = (const float*)d_in[13];
    const float* wlv   = (const float*)d_in[14];
    float* out = (float*)d_out;

    const int qpre_smem = 16512 * 4;   // 66,048 B
    cudaFuncSetAttribute(ek_qpre_kernel, cudaFuncAttributeMaxDynamicSharedMemorySize, qpre_smem);
    cudaFuncSetAttribute(ek_mlp_kernel,  cudaFuncAttributeMaxDynamicSharedMemorySize, MLP_SMEM);

    // launch index 3 (ncu capture slot) = ek_mlp_kernel
    ek_zero_kernel<<<1024, 256>>>();
    ek_qpre_kernel<<<500, 256, qpre_smem>>>(nodef, wdot, 0);
    ek_qpre_kernel<<<500, 256, qpre_smem>>>(nodef, wdot, 5000);
    ek_mlp_kernel<<<N_EDGES / 64, 256, MLP_SMEM>>>(xattr, wk1, bk1, wk2, wv1, bv1, wv2);
    ek_edge_kernel<<<N_EDGES / 8, 256>>>(esrc, edst, eattr, ecut, nodef);
    ek_out_kernel<<<N_NODES / 10, 128>>>(wls, wlv, out);
}

// round 17
// speedup vs baseline: 1.1645x; 1.0973x over previous
#include <cuda_runtime.h>
#include <cuda_bf16.h>
#include <math.h>
#include <stdint.h>

#define N_NODES 10000
#define N_EDGES 320000
#define MUL 32

__device__ __align__(16) float g_wkv [N_EDGES * 256];   // per-edge MLP outputs [wk(128)|wv(128)]
__device__ __align__(16) float g_qpre[N_NODES * 1024];  // per-node precomputed query side
__device__ __align__(16) float g_z   [N_NODES * 4];     // attention normalizer per head
__device__ __align__(16) float g_agg [N_NODES * 256];   // unnormalized aggregation

#define INV3F 0.57735026918962576f
#define INVFAN 0.015625f

// ---------------------------------------------------------------- f32x2 helpers
__device__ __forceinline__ uint64_t pack2(float lo, float hi) {
    uint64_t r; asm("mov.b64 %0, {%1, %2};" : "=l"(r) : "f"(lo), "f"(hi)); return r;
}
__device__ __forceinline__ void unpack2(uint64_t v, float& lo, float& hi) {
    asm("mov.b64 {%0, %1}, %2;" : "=f"(lo), "=f"(hi) : "l"(v));
}
__device__ __forceinline__ void fmaX2(uint64_t& c, uint64_t a, uint64_t b) {
    asm("fma.rn.f32x2 %0, %1, %2, %0;" : "+l"(c) : "l"(a), "l"(b));
}

// ---------------------------------------------------------------- zero scratch
__global__ void ek_zero_kernel() {
    int i = blockIdx.x * blockDim.x + threadIdx.x;
    int stride = gridDim.x * blockDim.x;
    float4 z4 = make_float4(0.f, 0.f, 0.f, 0.f);
    for (int j = i; j < N_NODES * 64; j += stride) ((float4*)g_agg)[j] = z4;
    for (int j = i; j < N_NODES;      j += stride) ((float4*)g_z)[j]   = z4;
}

// ---------------------------------------------------------------- Qpre as tiled f32x2 GEMM
// For part p: C[R x 128] = A[R x 32] * Wp[32 x 128(h,v)], scaled.
//   p<2 : R=10000 rows = nodes,  A[r][u] = nodef[r][u]           (xs)
//   p>=2: R=30000 rows = (n,d),  A[r][u] = nodef[n][32+3u+d]     (xv)
// Output col c = h*32+v -> g_qpre[n*1024 + h*256 + off_p(+d*32) + v].
// Block: 64 rows x 128 cols, 128 threads = 8 pt(4 row-pairs) x 16 ot(8 cols).
// A row-pairs are adjacent floats -> direct u64 loads, no pack movs.
__global__ void __launch_bounds__(128) ek_qpre_kernel(const float* __restrict__ nodef,
                                                      const float* __restrict__ wdot,
                                                      int pbase) {
    __shared__ float s_A[32 * 64];    //  8KB [u][row]
    __shared__ float s_w[32 * 128];   // 16KB [u][c]
    int t = threadIdx.x;
    int p = pbase + blockIdx.y;
    int R = (p < 2) ? N_NODES : (3 * N_NODES);
    int r0 = blockIdx.x * 64;
    if (r0 >= R) return;

    for (int i = t; i < 4096; i += 128) {
        int u = i >> 7, c = i & 127;
        s_w[i] = wdot[p * 4096 + (c >> 5) * 1024 + u * 32 + (c & 31)];
    }
    for (int i = t; i < 2048; i += 128) {
        int u = i >> 6, r = i & 63;
        int rr = r0 + r;
        float val = 0.f;
        if (rr < R) {
            if (p < 2) val = nodef[(size_t)rr * 128 + u];
            else { int n = rr / 3, d = rr - n * 3; val = nodef[(size_t)n * 128 + 32 + 3 * u + d]; }
        }
        s_A[u * 64 + r] = val;
    }
    __syncthreads();

    int pt = t & 7, ot = t >> 3;
    const uint64_t* Ap = (const uint64_t*)s_A + pt * 4;   // + k*32 (u64/k-row)
    const float*    wp = s_w + ot * 8;                    // + k*128

    uint64_t acc[4][8];
#pragma unroll
    for (int q = 0; q < 4; q++)
#pragma unroll
        for (int o = 0; o < 8; o++) acc[q][o] = 0ull;

#pragma unroll
    for (int k = 0; k < 32; k++) {
        ulonglong2 a01 = *(const ulonglong2*)(Ap + k * 32);
        ulonglong2 a23 = *(const ulonglong2*)(Ap + k * 32 + 2);
        float4 w0  = *(const float4*)(wp + k * 128);
        float4 w1v = *(const float4*)(wp + k * 128 + 4);
        uint64_t hx[4] = { a01.x, a01.y, a23.x, a23.y };
        uint64_t wd[8] = { pack2(w0.x, w0.x), pack2(w0.y, w0.y), pack2(w0.z, w0.z), pack2(w0.w, w0.w),
                           pack2(w1v.x, w1v.x), pack2(w1v.y, w1v.y), pack2(w1v.z, w1v.z), pack2(w1v.w, w1v.w) };
#pragma unroll
        for (int q = 0; q < 4; q++)
#pragma unroll
            for (int o = 0; o < 8; o++) fmaX2(acc[q][o], hx[q], wd[o]);
    }

    float s = (p < 2) ? INVFAN : (INVFAN * INV3F);
    int cbase = ot * 8;
    int h = cbase >> 5, vb = cbase & 31;
    int off_h = h * 256 + ((p == 0) ? 0 : (p == 1) ? 32 : (p == 2) ? 64 : 160) + vb;

#pragma unroll
    for (int q = 0; q < 4; q++) {
        float lo[8], hi[8];
#pragma unroll
        for (int o = 0; o < 8; o++) { unpack2(acc[q][o], lo[o], hi[o]); lo[o] *= s; hi[o] *= s; }
#pragma unroll
        for (int s2 = 0; s2 < 2; s2++) {
            int rr = r0 + pt * 8 + q * 2 + s2;
            if (rr < R) {
                const float* v = s2 ? hi : lo;
                size_t base;
                if (p < 2) base = (size_t)rr * 1024 + off_h;
                else { int n = rr / 3, d = rr - n * 3; base = (size_t)n * 1024 + off_h + d * 32; }
                *(float4*)(g_qpre + base)     = make_float4(v[0], v[1], v[2], v[3]);
                *(float4*)(g_qpre + base + 4) = make_float4(v[4], v[5], v[6], v[7]);
            }
        }
    }
}

// ---------------------------------------------------------------- f32x2 dual MLP (R16, measured 317us)
#define HS 68
#define MLP_SMEM 104960
__global__ void __launch_bounds__(256, 2) ek_mlp_kernel(const float* __restrict__ xattr,
    const float* __restrict__ wk1, const float* __restrict__ bk1, const float* __restrict__ wk2,
    const float* __restrict__ wv1, const float* __restrict__ bv1, const float* __restrict__ wv2) {
    extern __shared__ float sm[];
    float* s_h  = sm;                 // [128 c][68] swizzled
    float* s_w2 = sm + 8704;          // [64 k][256 n]
    float* s_w1 = sm + 25088;
    float* s_b1 = sm + 26112;
    int t = threadIdx.x;
    int e0 = blockIdx.x * 64;

    for (int i = t; i < 8192; i += 256) {
        int k = i >> 7, n = i & 127;
        s_w2[k * 256 + n]       = wk2[i];
        s_w2[k * 256 + 128 + n] = wv2[i];
    }
    for (int i = t; i < 1024; i += 256) s_w1[i] = (i < 512) ? wk1[i] : wv1[i - 512];
    if (t < 128) s_b1[t] = (t < 64) ? bk1[t] : bv1[t - 64];
    __syncthreads();

    {
        int e = t & 63, grp = t >> 6;
        int part = grp >> 1, cb = (grp & 1) * 32;
        const float4* xp = (const float4*)(xattr + (size_t)(e0 + e) * 8);
        float4 xa = xp[0], xb = xp[1];
        const float* w1 = s_w1 + part * 512;
        const float* bb = s_b1 + part * 64;
        int esw = e + ((e >> 5) << 2);
        float* hout = s_h + (part * 64 + cb) * HS + esw;
#pragma unroll 8
        for (int cc = 0; cc < 32; cc++) {
            int c = cb + cc;
            float acc = xa.x * w1[c]       + xa.y * w1[64 + c]  + xa.z * w1[128 + c] + xa.w * w1[192 + c]
                      + xb.x * w1[256 + c] + xb.y * w1[320 + c] + xb.z * w1[384 + c] + xb.w * w1[448 + c];
            acc = acc * 0.35355339059327373f + bb[c];
            float u2 = 0.7978845608028654f * (acc + 0.044715f * acc * acc * acc);
            float th;
            asm("tanh.approx.f32 %0, %1;" : "=f"(th) : "f"(u2));
            hout[cc * HS] = 0.5f * acc * (1.f + th);
        }
    }
    __syncthreads();

    int pt = t & 7, ot = t >> 3;
    int eoff = pt * 8 + ((pt >= 4) ? 4 : 0);
    const float* hp = s_h + ((ot >= 16) ? 64 * HS : 0) + eoff;
    const float* wp = s_w2 + ot * 8;
    uint64_t acc[4][8];
#pragma unroll
    for (int p = 0; p < 4; p++)
#pragma unroll
        for (int o = 0; o < 8; o++) acc[p][o] = 0ull;

#pragma unroll 8
    for (int k = 0; k < 64; k++) {
        float4 h0 = *(const float4*)(hp + k * HS);
        float4 h1 = *(const float4*)(hp + k * HS + 4);
        float4 w0 = *(const float4*)(wp + k * 256);
        float4 w1v = *(const float4*)(wp + k * 256 + 4);
        uint64_t hx[4] = { pack2(h0.x, h0.y), pack2(h0.z, h0.w),
                           pack2(h1.x, h1.y), pack2(h1.z, h1.w) };
        uint64_t wd[8] = { pack2(w0.x, w0.x), pack2(w0.y, w0.y), pack2(w0.z, w0.z), pack2(w0.w, w0.w),
                           pack2(w1v.x, w1v.x), pack2(w1v.y, w1v.y), pack2(w1v.z, w1v.z), pack2(w1v.w, w1v.w) };
#pragma unroll
        for (int p = 0; p < 4; p++)
#pragma unroll
            for (int o = 0; o < 8; o++) fmaX2(acc[p][o], hx[p], wd[o]);
    }

    const float inv64 = 0.125f;
    int n0 = ot * 8;
#pragma unroll
    for (int p = 0; p < 4; p++) {
        int elo = e0 + pt * 8 + p * 2;
        float lo[8], hi[8];
#pragma unroll
        for (int o = 0; o < 8; o++) { unpack2(acc[p][o], lo[o], hi[o]); lo[o] *= inv64; hi[o] *= inv64; }
        float* d0 = g_wkv + (size_t)elo * 256 + n0;
        float* d1 = d0 + 256;
        __stcs((float4*)d0,       make_float4(lo[0], lo[1], lo[2], lo[3]));
        __stcs((float4*)(d0 + 4), make_float4(lo[4], lo[5], lo[6], lo[7]));
        __stcs((float4*)d1,       make_float4(hi[0], hi[1], hi[2], hi[3]));
        __stcs((float4*)(d1 + 4), make_float4(hi[4], hi[5], hi[6], hi[7]));
    }
}

// ---------------------------------------------------------------- edge megakernel (atomic, measured 213us)
__device__ __forceinline__ float feat_base(int i, const float* row,
                                           float ys, float yv0, float yv1, float yv2,
                                           int& widx) {
    if (i < 32) { widx = i; return row[i] * ys; }
    if (i < 64) {
        int u = i - 32; widx = i;
        return (row[32 + 3 * u] * yv0 + row[33 + 3 * u] * yv1 + row[34 + 3 * u] * yv2) * INV3F;
    }
    if (i < 160) {
        int tt = i - 64; int d = tt >> 5, u = tt & 31; widx = 64 + u;
        float yd = (d == 0) ? yv0 : ((d == 1) ? yv1 : yv2);
        return row[u] * yd;
    }
    {
        int tt = i - 160; int d = tt >> 5, u = tt & 31; widx = 96 + u;
        return row[32 + 3 * u + d] * ys;
    }
}
__device__ __forceinline__ int feat_head(int i) {
    if (i < 64) return (i & 31) >> 3;
    int tt = (i < 160) ? (i - 64) : (i - 160);
    return (tt & 31) >> 3;
}
__device__ __forceinline__ void red_v4(float* p, float a, float b, float c, float d) {
    asm volatile("red.global.add.v4.f32 [%0], {%1, %2, %3, %4};"
                 :: "l"(p), "f"(a), "f"(b), "f"(c), "f"(d) : "memory");
}

__global__ void __launch_bounds__(256) ek_edge_kernel(
    const int* __restrict__ esrc, const int* __restrict__ edst,
    const float* __restrict__ eattr, const float* __restrict__ ecut,
    const float* __restrict__ nodef) {
    __shared__ float s_row[8][136];
    __shared__ float s_w[8][256];
    int warp = threadIdx.x >> 5, lane = threadIdx.x & 31;
    int e = blockIdx.x * 8 + warp;
    if (e >= N_EDGES) return;

    int s = esrc[e], dd = edst[e];
    float4 ea = *(const float4*)(eattr + (size_t)e * 4);
    float ys = ea.x, yv0 = ea.y, yv1 = ea.z, yv2 = ea.w;
    float cw = ecut[e];

    *(float4*)&s_row[warp][lane * 4] = *(const float4*)(nodef + (size_t)s * 128 + lane * 4);
    const float4* wv4 = (const float4*)(g_wkv + (size_t)e * 256);
    *(float4*)&s_w[warp][lane * 4]       = __ldcs(wv4 + lane);
    *(float4*)&s_w[warp][128 + lane * 4] = __ldcs(wv4 + 32 + lane);
    __syncwarp();

    const float* row = s_row[warp];
    const float* wk  = s_w[warp];
    int iA = 4 * lane, iB = 128 + 4 * lane;

    float bA[4], bB[4];
    int   xA[4], xB[4];
#pragma unroll
    for (int j = 0; j < 4; j++) {
        bA[j] = feat_base(iA + j, row, ys, yv0, yv1, yv2, xA[j]);
        bB[j] = feat_base(iB + j, row, ys, yv0, yv1, yv2, xB[j]);
    }

    float kA[4], kB[4];
#pragma unroll
    for (int j = 0; j < 4; j++) { kA[j] = wk[xA[j]] * bA[j]; kB[j] = wk[xB[j]] * bB[j]; }

    const float4* q = (const float4*)(g_qpre + (size_t)dd * 1024);
    float dh[4];
#pragma unroll
    for (int h = 0; h < 4; h++) {
        float4 qa = q[h * 64 + lane];
        float4 qb = q[h * 64 + 32 + lane];
        dh[h] = qa.x * kA[0] + qa.y * kA[1] + qa.z * kA[2] + qa.w * kA[3]
              + qb.x * kB[0] + qb.y * kB[1] + qb.z * kB[2] + qb.w * kB[3];
    }
#pragma unroll
    for (int off = 16; off; off >>= 1) {
#pragma unroll
        for (int h = 0; h < 4; h++) dh[h] += __shfl_xor_sync(0xffffffffu, dh[h], off);
    }

    float ew[4], sa[4];
#pragma unroll
    for (int h = 0; h < 4; h++) {
        ew[h] = cw * expf(dh[h]);
        sa[h] = sqrtf(ew[h]);     // sqrt(expw); /sqrt(z) deferred to epilogue
    }
    if (lane == 0) red_v4(g_z + (size_t)dd * 4, ew[0], ew[1], ew[2], ew[3]);

    const float* wv = wk + 128;
    float vA[4], vB[4];
#pragma unroll
    for (int j = 0; j < 4; j++) {
        vA[j] = wv[xA[j]] * bA[j] * sa[feat_head(iA + j)];
        vB[j] = wv[xB[j]] * bB[j] * sa[feat_head(iB + j)];
    }
    red_v4(g_agg + (size_t)dd * 256 + iA, vA[0], vA[1], vA[2], vA[3]);
    red_v4(g_agg + (size_t)dd * 256 + iB, vB[0], vB[1], vB[2], vB[3]);
}

// ---------------------------------------------------------------- node epilogue
__global__ void __launch_bounds__(128) ek_out_kernel(const float* __restrict__ wls,
                                                     const float* __restrict__ wlv,
                                                     float* __restrict__ out) {
    __shared__ float s_ws[2048];
    __shared__ float s_wv[2048];
    __shared__ float s_s[64];
    __shared__ float s_v[192];
    __shared__ float s_sc[4];
    int t = threadIdx.x;
    for (int i = t; i < 2048; i += 128) { s_ws[i] = wls[i]; s_wv[i] = wlv[i]; }
    const float inv_l = 0.125f;

    for (int nn = 0; nn < 10; nn++) {
        int n = blockIdx.x * 10 + nn;
        __syncthreads();
        if (t < 4) {
            float zz = g_z[(size_t)n * 4 + t];
            s_sc[t] = (zz == 0.f) ? 1.f : (1.0f / sqrtf(zz));
        }
        __syncthreads();
        for (int i = t; i < 256; i += 128) {
            float val = g_agg[(size_t)n * 256 + i];
            if (i < 64) {
                s_s[i] = val * s_sc[(i & 31) >> 3];
            } else {
                int f = i - 64;
                int blk = (f < 96) ? 0 : 1;
                int r = f - blk * 96;
                int d = r >> 5, uu = r & 31;
                s_v[d * 64 + blk * 32 + uu] = val * s_sc[uu >> 3];
            }
        }
        __syncthreads();
        if (t < 32) {
            int w = t;
            float acc = 0.f;
#pragma unroll
            for (int u = 0; u < 64; u++) acc += s_s[u] * s_ws[u * 32 + w];
            out[(size_t)n * 128 + w] = acc * inv_l;
        } else {
            int o = t - 32;
            int d = o >> 5, w = o & 31;
            float acc = 0.f;
#pragma unroll
            for (int u = 0; u < 64; u++) acc += s_v[d * 64 + u] * s_wv[u * 32 + w];
            out[(size_t)n * 128 + 32 + w * 3 + d] = acc * inv_l;
        }
    }
}

// ---------------------------------------------------------------- launch
extern "C" void kernel_launch(void* const* d_in, const int* in_sizes, int n_in,
                              void* d_out, int out_size) {
    const int*   esrc  = (const int*)d_in[0];
    const int*   edst  = (const int*)d_in[1];
    const float* xattr = (const float*)d_in[2];
    const float* eattr = (const float*)d_in[3];
    const float* ecut  = (const float*)d_in[4];
    const float* nodef = (const float*)d_in[5];
    const float* wk1   = (const float*)d_in[6];
    const float* bk1   = (const float*)d_in[7];
    const float* wk2   = (const float*)d_in[8];
    const float* wv1   = (const float*)d_in[9];
    const float* bv1   = (const float*)d_in[10];
    const float* wv2   = (const float*)d_in[11];
    const float* wdot  = (const float*)d_in[12];
    const float* wls   = (const float*)d_in[13];
    const float* wlv   = (const float*)d_in[14];
    float* out = (float*)d_out;

    cudaFuncSetAttribute(ek_mlp_kernel, cudaFuncAttributeMaxDynamicSharedMemorySize, MLP_SMEM);

    // slot 3 (ncu capture) = qpre p2/p3 launch
    ek_zero_kernel<<<1024, 256>>>();
    ek_mlp_kernel<<<N_EDGES / 64, 256, MLP_SMEM>>>(xattr, wk1, bk1, wk2, wv1, bv1, wv2);
    dim3 qgridA(157, 2);   // p0, p1: 10000 rows
    ek_qpre_kernel<<<qgridA, 128>>>(nodef, wdot, 0);
    dim3 qgridB(469, 2);   // p2, p3: 30000 rows
    ek_qpre_kernel<<<qgridB, 128>>>(nodef, wdot, 2);
    ek_edge_kernel<<<N_EDGES / 8, 256>>>(esrc, edst, eattr, ecut, nodef);
    ek_out_kernel<<<N_NODES / 10, 128>>>(wls, wlv, out);
}